// round 12
// baseline (speedup 1.0000x reference)
#include <cuda_runtime.h>
#include <cuda_bf16.h>
#include <math.h>
#include <stdint.h>

#define HEADS 4
#define POSN 961
#define PD 8
#define TOK 131072

// Scratch (allocation-free: __device__ globals)
__device__ float g_pos[POSN * HEADS];
// bias * log2(e), bf16 pairs pre-swizzled into mma-fragment order:
// [head][rowblk(16)][chunk(8)][lane(32)][8 words]
__device__ uint32_t g_bias2w[HEADS * 16 * 8 * 32 * 8];
__device__ uint32_t g_wh[384 * 64];                  // qkv W as bf16 pairs [col][64w]

__device__ __forceinline__ float fast_ex2(float x) {
    float y; asm("ex2.approx.f32 %0, %1;" : "=f"(y) : "f"(x)); return y;
}
// pack two fp32 -> bf16x2: hi -> upper 16 bits, lo -> lower 16 bits
__device__ __forceinline__ uint32_t packbf(float hi, float lo) {
    uint32_t u; asm("cvt.rn.bf16x2.f32 %0, %1, %2;" : "=r"(u) : "f"(hi), "f"(lo)); return u;
}
__device__ __forceinline__ uint32_t smem_u32(const void* p) {
    uint32_t a;
    asm("{ .reg .u64 t; cvta.to.shared.u64 t, %1; cvt.u32.u64 %0, t; }" : "=r"(a) : "l"(p));
    return a;
}
__device__ __forceinline__ void mma_bf16(float* d, const uint32_t* a, const uint32_t* b) {
    asm volatile("mma.sync.aligned.m16n8k16.row.col.f32.bf16.bf16.f32 "
        "{%0,%1,%2,%3}, {%4,%5,%6,%7}, {%8,%9}, {%0,%1,%2,%3};"
        : "+f"(d[0]), "+f"(d[1]), "+f"(d[2]), "+f"(d[3])
        : "r"(a[0]), "r"(a[1]), "r"(a[2]), "r"(a[3]), "r"(b[0]), "r"(b[1]));
}
__device__ __forceinline__ void ldsm4(uint32_t* r, uint32_t addr) {
    asm volatile("ldmatrix.sync.aligned.m8n8.x4.shared.b16 {%0,%1,%2,%3}, [%4];"
        : "=r"(r[0]), "=r"(r[1]), "=r"(r[2]), "=r"(r[3]) : "r"(addr));
}
__device__ __forceinline__ void ldsm4t(uint32_t* r, uint32_t addr) {
    asm volatile("ldmatrix.sync.aligned.m8n8.x4.trans.shared.b16 {%0,%1,%2,%3}, [%4];"
        : "=r"(r[0]), "=r"(r[1]), "=r"(r[2]), "=r"(r[3]) : "r"(addr));
}
__device__ __forceinline__ void cp16(uint32_t dst, const void* src) {
    asm volatile("cp.async.cg.shared.global [%0], [%1], 16;" :: "r"(dst), "l"(src));
}
#define CP_COMMIT() asm volatile("cp.async.commit_group;" ::: "memory")
#define CP_WAIT0()  asm volatile("cp.async.wait_group 0;" ::: "memory")

// ---------------------------------------------------------------------------
// Kernel 1: DynamicPosBias MLP (961 rows, hidden 8). One thread per row.
// ---------------------------------------------------------------------------
__device__ __forceinline__ void dpb_layer(const float* in, float* outp,
                                          const float* g, const float* bt,
                                          const float* w, const float* bs, int OUT) {
    float mean = 0.f;
    #pragma unroll
    for (int i = 0; i < PD; i++) mean += in[i];
    mean *= 0.125f;
    float var = 0.f;
    #pragma unroll
    for (int i = 0; i < PD; i++) { float d = in[i] - mean; var += d * d; }
    var *= 0.125f;
    float r = rsqrtf(var + 1e-5f);
    float a[PD];
    #pragma unroll
    for (int i = 0; i < PD; i++)
        a[i] = fmaxf((in[i] - mean) * r * g[i] + bt[i], 0.f);
    for (int o = 0; o < OUT; o++) {
        float s = bs[o];
        #pragma unroll
        for (int j = 0; j < PD; j++) s += a[j] * w[o * PD + j];
        outp[o] = s;
    }
}

__global__ void dpb_kernel(const float* __restrict__ pp_w, const float* __restrict__ pp_b,
                           const float* __restrict__ l1g, const float* __restrict__ l1b,
                           const float* __restrict__ f1w, const float* __restrict__ f1b,
                           const float* __restrict__ l2g, const float* __restrict__ l2b,
                           const float* __restrict__ f2w, const float* __restrict__ f2b,
                           const float* __restrict__ l3g, const float* __restrict__ l3b,
                           const float* __restrict__ f3w, const float* __restrict__ f3b) {
    int t = blockIdx.x * blockDim.x + threadIdx.x;
    if (t >= POSN) return;
    float by = (float)(t / 31 - 15);
    float bx = (float)(t % 31 - 15);
    float p0[PD], p1[PD], p2[PD], f[HEADS];
    #pragma unroll
    for (int i = 0; i < PD; i++)
        p0[i] = by * pp_w[i * 2 + 0] + bx * pp_w[i * 2 + 1] + pp_b[i];
    dpb_layer(p0, p1, l1g, l1b, f1w, f1b, PD);
    dpb_layer(p1, p2, l2g, l2b, f2w, f2b, PD);
    dpb_layer(p2, f, l3g, l3b, f3w, f3b, HEADS);
    #pragma unroll
    for (int i = 0; i < HEADS; i++) g_pos[t * HEADS + i] = f[i];
}

// Combined prep: W -> bf16 pairs (24576 threads) + bias expansion into
// mma-fragment order (16384 threads).
__global__ void prep_kernel(const float* __restrict__ qkvw) {
    int gid = blockIdx.x * blockDim.x + threadIdx.x;
    if (gid < 24576) {
        float2 v = ((const float2*)qkvw)[gid];
        g_wh[gid] = packbf(v.y, v.x);
        return;
    }
    int idx = gid - 24576;                 // 16384 threads
    int lane = idx & 31;
    int ch = (idx >> 5) & 7;
    int rb = (idx >> 8) & 15;
    int head = idx >> 12;
    int l4 = lane >> 2, qd = lane & 3;
    const float L2E = 1.4426950408889634f;
    uint32_t w[8];
    #pragma unroll
    for (int nt = 0; nt < 4; nt++) {
        int col0 = ch * 32 + nt * 8 + 2 * qd;
        #pragma unroll
        for (int h = 0; h < 2; h++) {
            int row = rb * 16 + l4 + h * 8;
            int b0 = ((row >> 4) - (col0 >> 4) + 15) * 31 + ((row & 15) - (col0 & 15) + 15);
            int c1 = col0 + 1;
            int b1 = ((row >> 4) - (c1 >> 4) + 15) * 31 + ((row & 15) - (c1 & 15) + 15);
            float f0 = g_pos[b0 * HEADS + head] * L2E;
            float f1 = g_pos[b1 * HEADS + head] * L2E;
            w[2 * nt + h] = packbf(f1, f0);
        }
    }
    uint4* dst = (uint4*)(g_bias2w + (size_t)idx * 8);
    dst[0] = make_uint4(w[0], w[1], w[2], w[3]);
    dst[1] = make_uint4(w[4], w[5], w[6], w[7]);
}

// ---------------------------------------------------------------------------
// Kernel 2: FUSED LN + QKV-GEMM (96 cols for this head) + attention.
// Block per (window, head), 256 threads. Warp w owns window rows 32w..32w+31:
//  - LN its rows into a private A slab [32][68w]
//  - GEMM (A slab x W-slice): K,V,Q C-frags per 16-row m-tile; Q converts
//    in-register to QK A-frags; K/V frags stored into the freed A-slab section
//  - attention: same as R11 (swizzled bias, no max-sub), K/V ldsm from slabs.
// smem: A/KV slabs 8*8704B = 69632 + W [96][68w] 26112 = 95744B -> 2 CTAs/SM.
// ---------------------------------------------------------------------------
#define W_OFF 17408                      // word offset of W region
#define F_SMEM 95744

__global__ void __launch_bounds__(256, 2)
fused_kernel(const float* __restrict__ x,
             const float* __restrict__ ng, const float* __restrict__ nb,
             const float* __restrict__ qkvb, float* __restrict__ out) {
    extern __shared__ uint32_t smw[];
    uint32_t sb = smem_u32(smw);

    int tid = threadIdx.x;
    int warp = tid >> 5, lane = tid & 31;
    int qd = lane & 3, l4 = lane >> 2;
    int head = blockIdx.x & 3;
    int win = blockIdx.x >> 2;
    int b = win >> 8, wi = win & 255;
    int wr = wi >> 4, wc = wi & 15;
    int tbase = b * 65536 + wr * 4096 + wc * 16;

    // stage W-slice for this head: 96 cols x 64 words via cp.async
    #pragma unroll
    for (int i = 0; i < 6; i++) {
        int idx = tid + i * 256;             // 0..1535
        int c = idx >> 4, s = idx & 15;
        int gcol = (c >> 5) * 128 + head * 32 + (c & 31);
        cp16(sb + (uint32_t)((W_OFF + c * 68 + s * 4) * 4),
             g_wh + gcol * 64 + s * 4);
    }
    CP_COMMIT();

    // LN: 32 rows per warp into private A slab (overlaps W copy)
    int slabW = warp * 2176;                 // word offset of this warp's slab
    #pragma unroll 4
    for (int i = 0; i < 32; i++) {
        int n = warp * 32 + i;
        int t = tbase + (n >> 4) * 256 + (n & 15);
        float4 v = ((const float4*)x)[t * 32 + lane];
        float s = v.x + v.y + v.z + v.w;
        float ss = v.x * v.x + v.y * v.y + v.z * v.z + v.w * v.w;
        #pragma unroll
        for (int o = 16; o; o >>= 1) {
            s  += __shfl_xor_sync(0xffffffffu, s, o);
            ss += __shfl_xor_sync(0xffffffffu, ss, o);
        }
        float mean = s * (1.f / 128.f);
        float var = ss * (1.f / 128.f) - mean * mean;
        float rstd = rsqrtf(var + 1e-5f);
        float4 g4 = ((const float4*)ng)[lane];
        float4 b4 = ((const float4*)nb)[lane];
        uint2 u;
        u.x = packbf((v.y - mean) * rstd * g4.y + b4.y, (v.x - mean) * rstd * g4.x + b4.x);
        u.y = packbf((v.w - mean) * rstd * g4.w + b4.w, (v.z - mean) * rstd * g4.z + b4.z);
        *(uint2*)(smw + slabW + i * 68 + lane * 2) = u;
    }
    CP_WAIT0();
    __syncthreads();

    // ---- GEMM: per m-tile compute K,V,Q; store K/V into freed slab section --
    int arow_off = ((lane >> 3) & 1) * 8 + (lane & 7);
    int awcol = ((lane >> 4) & 1) * 4;
    int brow = ((lane >> 4) & 1) * 8 + (lane & 7);
    int bword = ((lane >> 3) & 1) * 4;

    uint32_t aQ[2][2][4];

#define GEMM_GRP(C, GBASE)                                                     \
    do {                                                                       \
        _Pragma("unroll")                                                      \
        for (int ks = 0; ks < 8; ks++) {                                       \
            uint32_t aA[4];                                                    \
            ldsm4(aA, sb + (uint32_t)((slabW + (mt * 16 + arow_off) * 68 + ks * 8 + awcol) * 4)); \
            _Pragma("unroll")                                                  \
            for (int cg = 0; cg < 2; cg++) {                                   \
                uint32_t br[4];                                                \
                ldsm4(br, sb + (uint32_t)((W_OFF + ((GBASE) + cg * 16 + brow) * 68 + ks * 8 + bword) * 4)); \
                mma_bf16(C[2 * cg + 0], aA, br + 0);                           \
                mma_bf16(C[2 * cg + 1], aA, br + 2);                           \
            }                                                                  \
        }                                                                      \
    } while (0)

    #pragma unroll 1
    for (int mt = 0; mt < 2; mt++) {
        float Ck[4][4], Cv[4][4], Cq[4][4];
        #pragma unroll
        for (int nt = 0; nt < 4; nt++)
            #pragma unroll
            for (int c = 0; c < 4; c++) { Ck[nt][c] = 0.f; Cv[nt][c] = 0.f; Cq[nt][c] = 0.f; }

        GEMM_GRP(Ck, 32);
        GEMM_GRP(Cv, 64);
        GEMM_GRP(Cq, 0);

        // Q: add bias, convert C-frags -> QK A-frags (in registers)
        #pragma unroll
        for (int ks2 = 0; ks2 < 2; ks2++) {
            float2 b0 = *(const float2*)(qkvb + head * 32 + (2 * ks2) * 8 + 2 * qd);
            float2 b1 = *(const float2*)(qkvb + head * 32 + (2 * ks2 + 1) * 8 + 2 * qd);
            aQ[mt][ks2][0] = packbf(Cq[2 * ks2][1] + b0.y, Cq[2 * ks2][0] + b0.x);
            aQ[mt][ks2][1] = packbf(Cq[2 * ks2][3] + b0.y, Cq[2 * ks2][2] + b0.x);
            aQ[mt][ks2][2] = packbf(Cq[2 * ks2 + 1][1] + b1.y, Cq[2 * ks2 + 1][0] + b1.x);
            aQ[mt][ks2][3] = packbf(Cq[2 * ks2 + 1][3] + b1.y, Cq[2 * ks2 + 1][2] + b1.x);
        }

        // K/V: add bias, pack, store into freed A-slab section (mt)
        int secbase = slabW + mt * 1088;     // K at +0 (16 rows x 20w), V at +320
        #pragma unroll
        for (int nt = 0; nt < 4; nt++) {
            float2 bk = *(const float2*)(qkvb + 128 + head * 32 + nt * 8 + 2 * qd);
            float2 bv = *(const float2*)(qkvb + 256 + head * 32 + nt * 8 + 2 * qd);
            #pragma unroll
            for (int h = 0; h < 2; h++) {
                int word = secbase + (8 * h + l4) * 20 + nt * 4 + qd;
                smw[word]       = packbf(Ck[nt][2 * h + 1] + bk.y, Ck[nt][2 * h] + bk.x);
                smw[word + 320] = packbf(Cv[nt][2 * h + 1] + bv.y, Cv[nt][2 * h] + bv.x);
            }
        }
    }
    __syncthreads();

    // ---- attention ----
    int r0q = warp * 32;
    const float qscale = 0.17677669529663687f * 1.4426950408889634f;  // d^-0.5*log2e

    uint32_t kLaneOff, vLaneOff;
    {
        int krow = ((lane >> 4) & 1) * 8 + (lane & 7);
        int kword = ((lane >> 3) & 1) * 4;
        kLaneOff = (uint32_t)((krow * 20 + kword) * 4);
        int vrow = ((lane >> 3) & 1) * 8 + (lane & 7);
        int vword = ((lane >> 4) & 1) * 4;
        vLaneOff = (uint32_t)((vrow * 20 + vword) * 4);
    }
    const uint32_t* bias0 = g_bias2w
        + ((((size_t)head * 16 + warp * 2) * 8) * 32 + lane) * 8;

    float oacc[2][4][4];
    #pragma unroll
    for (int mt = 0; mt < 2; mt++)
        #pragma unroll
        for (int nv = 0; nv < 4; nv++)
            #pragma unroll
            for (int c = 0; c < 4; c++) oacc[mt][nv][c] = 0.f;
    float lacc[2][2] = {{0.f, 0.f}, {0.f, 0.f}};

    #pragma unroll 1
    for (int ch = 0; ch < 8; ch++) {
        int c0 = ch * 32;

        // ---- QK: 32 rows x 32 keys ----
        float acc[2][4][4];
        #pragma unroll
        for (int mt = 0; mt < 2; mt++)
            #pragma unroll
            for (int nt = 0; nt < 4; nt++)
                #pragma unroll
                for (int c = 0; c < 4; c++) acc[mt][nt][c] = 0.f;

        #pragma unroll
        for (int g = 0; g < 2; g++) {
            int row16 = c0 + g * 16;
            uint32_t ka = sb + (uint32_t)((((row16 >> 5) * 2176) + ((row16 >> 4) & 1) * 1088) * 4) + kLaneOff;
            #pragma unroll
            for (int ks = 0; ks < 2; ks++) {
                uint32_t kr[4];
                ldsm4(kr, ka + ks * 32);
                #pragma unroll
                for (int mt = 0; mt < 2; mt++) {
                    mma_bf16(acc[mt][2 * g + 0], aQ[mt][ks], kr + 0);
                    mma_bf16(acc[mt][2 * g + 1], aQ[mt][ks], kr + 2);
                }
            }
        }

        // ---- bias (fragment-swizzled, coalesced) + ex2 + row-sum + pack ----
        uint32_t pA[2][2][4];
        #pragma unroll
        for (int mt = 0; mt < 2; mt++) {
            const uint4* bp = (const uint4*)(bias0 + ((mt * 8 + ch) * 32) * 8);
            uint4 w0 = bp[0];
            uint4 w1 = bp[1];
            uint32_t bw[8] = {w0.x, w0.y, w0.z, w0.w, w1.x, w1.y, w1.z, w1.w};
            #pragma unroll
            for (int nt = 0; nt < 4; nt++) {
                uint32_t blo = bw[2 * nt];
                uint32_t bhi = bw[2 * nt + 1];
                float p0 = fast_ex2(acc[mt][nt][0] * qscale + __uint_as_float(blo << 16));
                float p1 = fast_ex2(acc[mt][nt][1] * qscale + __uint_as_float(blo & 0xffff0000u));
                float p2 = fast_ex2(acc[mt][nt][2] * qscale + __uint_as_float(bhi << 16));
                float p3 = fast_ex2(acc[mt][nt][3] * qscale + __uint_as_float(bhi & 0xffff0000u));
                lacc[mt][0] += p0 + p1;
                lacc[mt][1] += p2 + p3;
                acc[mt][nt][0] = p0; acc[mt][nt][1] = p1;
                acc[mt][nt][2] = p2; acc[mt][nt][3] = p3;
            }
            #pragma unroll
            for (int kt = 0; kt < 2; kt++) {
                pA[mt][kt][0] = packbf(acc[mt][2 * kt][1], acc[mt][2 * kt][0]);
                pA[mt][kt][1] = packbf(acc[mt][2 * kt][3], acc[mt][2 * kt][2]);
                pA[mt][kt][2] = packbf(acc[mt][2 * kt + 1][1], acc[mt][2 * kt + 1][0]);
                pA[mt][kt][3] = packbf(acc[mt][2 * kt + 1][3], acc[mt][2 * kt + 1][2]);
            }
        }

        // ---- PV over this chunk's 32 keys (V via ldmatrix.trans) ----
        #pragma unroll
        for (int kt = 0; kt < 2; kt++) {
            int row16 = c0 + kt * 16;
            uint32_t va = sb + (uint32_t)((((row16 >> 5) * 2176) + ((row16 >> 4) & 1) * 1088 + 320) * 4) + vLaneOff;
            #pragma unroll
            for (int dh = 0; dh < 2; dh++) {
                uint32_t vr[4];
                ldsm4t(vr, va + dh * 32);
                #pragma unroll
                for (int mt = 0; mt < 2; mt++) {
                    mma_bf16(oacc[mt][2 * dh + 0], pA[mt][kt], vr + 0);
                    mma_bf16(oacc[mt][2 * dh + 1], pA[mt][kt], vr + 2);
                }
            }
        }
    }

    // ---- final row-sum reduce (across the 4 qd lanes) + epilogue ----
    #pragma unroll
    for (int mt = 0; mt < 2; mt++)
        #pragma unroll
        for (int h = 0; h < 2; h++) {
            float l = lacc[mt][h];
            l += __shfl_xor_sync(0xffffffffu, l, 1);
            l += __shfl_xor_sync(0xffffffffu, l, 2);
            lacc[mt][h] = 1.f / l;
        }

    #pragma unroll
    for (int mt = 0; mt < 2; mt++)
        #pragma unroll
        for (int h = 0; h < 2; h++) {
            int row = r0q + mt * 16 + 8 * h + l4;
            float inv = lacc[mt][h];
            int t = tbase + (row >> 4) * 256 + (row & 15);
            const float* xp = x + (size_t)t * 128 + head * 32;
            float* op = out + (size_t)t * 128 + head * 32;
            #pragma unroll
            for (int nv = 0; nv < 4; nv++) {
                int dcol = nv * 8 + 2 * qd;
                float2 xv = *(const float2*)(xp + dcol);
                float2 o;
                o.x = xv.x + oacc[mt][nv][2 * h + 0] * inv;
                o.y = xv.y + oacc[mt][nv][2 * h + 1] * inv;
                *(float2*)(op + dcol) = o;
            }
        }
}

// ---------------------------------------------------------------------------
extern "C" void kernel_launch(void* const* d_in, const int* in_sizes, int n_in,
                              void* d_out, int out_size) {
    const float* x    = (const float*)d_in[0];
    const float* n1g  = (const float*)d_in[1];
    const float* n1b  = (const float*)d_in[2];
    const float* qkvw = (const float*)d_in[3];
    const float* qkvb = (const float*)d_in[4];
    const float* ppw  = (const float*)d_in[5];
    const float* ppb  = (const float*)d_in[6];
    const float* l1g  = (const float*)d_in[7];
    const float* l1b  = (const float*)d_in[8];
    const float* f1w  = (const float*)d_in[9];
    const float* f1b  = (const float*)d_in[10];
    const float* l2g  = (const float*)d_in[11];
    const float* l2b  = (const float*)d_in[12];
    const float* f2w  = (const float*)d_in[13];
    const float* f2b  = (const float*)d_in[14];
    const float* l3g  = (const float*)d_in[15];
    const float* l3b  = (const float*)d_in[16];
    const float* f3w  = (const float*)d_in[17];
    const float* f3b  = (const float*)d_in[18];
    float* out = (float*)d_out;

    cudaFuncSetAttribute(fused_kernel, cudaFuncAttributeMaxDynamicSharedMemorySize, F_SMEM);

    dpb_kernel<<<8, 128>>>(ppw, ppb, l1g, l1b, f1w, f1b,
                           l2g, l2b, f2w, f2b, l3g, l3b, f3w, f3b);
    prep_kernel<<<160, 256>>>(qkvw);
    fused_kernel<<<2048, 256, F_SMEM>>>(x, n1g, n1b, qkvb, out);
}